// round 1
// baseline (speedup 1.0000x reference)
#include <cuda_runtime.h>

// OriginNoiseBilateral: 17x17 bilateral filter, 8 images, 3ch, 512x512, fp32 NCHW.
// Strategy: 16x16 output tile per 256-thread block, 32x32 float4 halo tile in smem.
// All scaling (255^2) and log2(e) folded into the exponent constants so each tap is
// 1 LDS.128 + ~12 FMA-pipe ops + 1 MUFU EX2.

namespace {
constexpr int H = 512, W = 512, C = 3;
constexpr int HW = H * W;
constexpr int TILE = 16;
constexpr int RMAX = 8;
constexpr int SDIM = TILE + 2 * RMAX;   // 32
}

__device__ __forceinline__ float ex2f(float x) {
    float y;
    asm("ex2.approx.ftz.f32 %0, %1;" : "=f"(y) : "f"(x));
    return y;
}

__global__ __launch_bounds__(256)
void bilateral_kernel(const float* __restrict__ img,
                      const float* __restrict__ params,
                      float* __restrict__ out)
{
    __shared__ float4 tile[SDIM * SDIM];   // 16 KB

    const int n   = blockIdx.z;
    const int tx  = threadIdx.x;           // 0..15
    const int ty  = threadIdx.y;           // 0..15
    const int tid = ty * TILE + tx;

    const int x0 = blockIdx.x * TILE - RMAX;   // halo origin
    const int y0 = blockIdx.y * TILE - RMAX;

    const float* im = img + (size_t)n * C * HW;

    // Per-image parameters (reference: window = int(p0)*14+3, sigma = p*99+1)
    const float p0 = params[n * 3 + 0];
    const float p1 = params[n * 3 + 1];
    const float p2 = params[n * 3 + 2];
    const int   win    = ((int)p0) * 14 + 3;
    const int   radius = (win - 1) >> 1;
    const int   r      = radius < RMAX ? radius : RMAX;
    const float sc = fmaf(p1, 99.0f, 1.0f);
    const float ss = fmaf(p2, 99.0f, 1.0f);
    // Fold 255^2 (reference scales pixels by 255) and log2(e) (we use ex2) in:
    const float LOG2E = 1.4426950408889634f;
    const float inv2c = 65025.0f * LOG2E / (2.0f * sc * sc);
    const float inv2s = LOG2E / (2.0f * ss * ss);

    // Cooperative halo load with edge clamp. 1024 entries / 256 threads = 4 each.
    #pragma unroll
    for (int i = tid; i < SDIM * SDIM; i += 256) {
        int sy = i / SDIM, sx = i % SDIM;
        int gy = min(max(y0 + sy, 0), H - 1);
        int gx = min(max(x0 + sx, 0), W - 1);
        int b  = gy * W + gx;
        tile[i] = make_float4(im[b], im[b + HW], im[b + 2 * HW], 0.0f);
    }
    __syncthreads();

    const float4 c = tile[(ty + RMAX) * SDIM + (tx + RMAX)];

    float num0 = 0.0f, num1 = 0.0f, num2 = 0.0f, den = 0.0f;

    if (r == RMAX) {
        // Hot path (params==1 -> radius 8). Inner dx loop fully unrolled so
        // dx*dx is a compile-time constant folded into the exponent FMA.
        #pragma unroll 1
        for (int dy = -RMAX; dy <= RMAX; dy++) {
            const float4* row = &tile[(ty + RMAX + dy) * SDIM + (tx + RMAX)];
            const float spy = (float)(dy * dy);
            #pragma unroll
            for (int dx = -RMAX; dx <= RMAX; dx++) {
                float4 s  = row[dx];
                float d0 = s.x - c.x;
                float d1 = s.y - c.y;
                float d2 = s.z - c.z;
                float dist2 = fmaf(d2, d2, fmaf(d1, d1, d0 * d0));
                float sp2   = spy + (float)(dx * dx);
                float arg   = fmaf(dist2, -inv2c, sp2 * (-inv2s));
                float w     = ex2f(arg);
                num0 = fmaf(w, s.x, num0);
                num1 = fmaf(w, s.y, num1);
                num2 = fmaf(w, s.z, num2);
                den += w;
            }
        }
    } else {
        // Generic radius (masked taps in the reference are exactly the taps
        // outside [-r, r]^2, so looping the restricted range is equivalent).
        for (int dy = -r; dy <= r; dy++) {
            const float4* row = &tile[(ty + RMAX + dy) * SDIM + (tx + RMAX)];
            const float spy = (float)(dy * dy);
            for (int dx = -r; dx <= r; dx++) {
                float4 s  = row[dx];
                float d0 = s.x - c.x;
                float d1 = s.y - c.y;
                float d2 = s.z - c.z;
                float dist2 = fmaf(d2, d2, fmaf(d1, d1, d0 * d0));
                float sp2   = spy + (float)(dx * dx);
                float arg   = fmaf(dist2, -inv2c, sp2 * (-inv2s));
                float w     = ex2f(arg);
                num0 = fmaf(w, s.x, num0);
                num1 = fmaf(w, s.y, num1);
                num2 = fmaf(w, s.z, num2);
                den += w;
            }
        }
    }

    const int ox = blockIdx.x * TILE + tx;
    const int oy = blockIdx.y * TILE + ty;
    const float inv = __fdividef(1.0f, den);
    float* o = out + (size_t)n * C * HW + oy * W + ox;
    o[0]      = num0 * inv;
    o[HW]     = num1 * inv;
    o[2 * HW] = num2 * inv;
}

extern "C" void kernel_launch(void* const* d_in, const int* in_sizes, int n_in,
                              void* d_out, int out_size) {
    const float* img    = (const float*)d_in[0];
    const float* params = (const float*)d_in[1];
    float*       outp   = (float*)d_out;
    const int N = in_sizes[1] / 3;   // 8 images
    dim3 block(TILE, TILE, 1);
    dim3 grid(W / TILE, H / TILE, N);
    bilateral_kernel<<<grid, block>>>(img, params, outp);
}

// round 2
// speedup vs baseline: 1.0784x; 1.0784x over previous
#include <cuda_runtime.h>

// OriginNoiseBilateral R2: 17x17 bilateral, 8x3x512x512 fp32 NCHW.
// V=4 vertical register blocking (85 LDS.128/output instead of 289) +
// dot-product color distance with |s|^2 * -inv2c precomputed into the tile's
// .w lane. Edge taps (rows and generic radius columns) masked branch-free by
// driving the exponent to -1e30 (ex2 -> 0).

namespace {
constexpr int H = 512, W = 512, C = 3;
constexpr int HW = H * W;
constexpr int RMAX = 8;
constexpr int BX = 32, BY = 8;       // 256 threads
constexpr int V  = 4;                 // vertical outputs per thread
constexpr int TW = BX;                // 32-wide output tile
constexpr int TH = BY * V;            // 32-tall output tile
constexpr int SW = TW + 2 * RMAX;     // 48
constexpr int SH = TH + 2 * RMAX;     // 48
constexpr float NEG_BIG = -1e30f;
}

__device__ __forceinline__ float ex2f(float x) {
    float y;
    asm("ex2.approx.ftz.f32 %0, %1;" : "=f"(y) : "f"(x));
    return y;
}

__global__ __launch_bounds__(256)
void bilateral_kernel(const float* __restrict__ img,
                      const float* __restrict__ params,
                      float* __restrict__ out)
{
    __shared__ float4 tile[SH * SW];   // 48*48*16 = 36864 B

    const int n   = blockIdx.z;
    const int tx  = threadIdx.x;       // 0..31
    const int ty  = threadIdx.y;       // 0..7
    const int tid = ty * BX + tx;

    const int x0 = blockIdx.x * TW - RMAX;   // halo origin in image coords
    const int y0 = blockIdx.y * TH - RMAX;

    const float* im = img + (size_t)n * C * HW;

    // Per-image parameters: window = int(p0)*14+3, sigma = p*99+1
    const float p0 = params[n * 3 + 0];
    const float p1 = params[n * 3 + 1];
    const float p2 = params[n * 3 + 2];
    const int   radius = ((((int)p0) * 14 + 3) - 1) >> 1;
    const int   r      = radius < RMAX ? radius : RMAX;
    const float sc = fmaf(p1, 99.0f, 1.0f);
    const float ss = fmaf(p2, 99.0f, 1.0f);
    const float LOG2E = 1.4426950408889634f;
    // 255^2 (reference pixel scaling) and log2(e) folded into the constants.
    const float inv2c = 65025.0f * LOG2E / (2.0f * sc * sc);
    const float inv2s = LOG2E / (2.0f * ss * ss);
    const float A = 2.0f * inv2c;      // coefficient of the dot product

    // Cooperative halo load with edge clamp; .w = -inv2c * |rgb|^2.
    #pragma unroll
    for (int i = tid; i < SH * SW; i += BX * BY) {
        int sy = i / SW, sx = i % SW;
        int gy = min(max(y0 + sy, 0), H - 1);
        int gx = min(max(x0 + sx, 0), W - 1);
        int b  = gy * W + gx;
        float a0 = im[b], a1 = im[b + HW], a2 = im[b + 2 * HW];
        float sq = fmaf(a2, a2, fmaf(a1, a1, a0 * a0));
        tile[i] = make_float4(a0, a1, a2, -inv2c * sq);
    }
    __syncthreads();

    // Per-dx spatial/mask terms (registers; indexed only with unrolled dx).
    float ct[2 * RMAX + 1];
    #pragma unroll
    for (int dx = 0; dx < 2 * RMAX + 1; dx++) {
        int d = dx - RMAX;
        int ad = d < 0 ? -d : d;
        ct[dx] = (ad <= r) ? ((float)(d * d)) * (-inv2s) : NEG_BIG;
    }

    // Centers for the V vertical outputs of this thread.
    float4 cc[V];
    #pragma unroll
    for (int v = 0; v < V; v++)
        cc[v] = tile[(ty * V + v + RMAX) * SW + (tx + RMAX)];

    float nx[V], ny[V], nz[V], den[V];
    #pragma unroll
    for (int v = 0; v < V; v++) { nx[v] = ny[v] = nz[v] = den[v] = 0.0f; }

    // Sliding window over V+16 rows; each loaded row serves all active outputs.
    #pragma unroll 1
    for (int i = 0; i < V + 2 * RMAX; i++) {
        const float4* row = &tile[(ty * V + i) * SW + tx];

        float rb[V];
        #pragma unroll
        for (int v = 0; v < V; v++) {
            int dy = i - RMAX - v;
            int ady = dy < 0 ? -dy : dy;
            rb[v] = (ady <= r)
                  ? fmaf((float)(dy * dy), -inv2s, cc[v].w)
                  : NEG_BIG;
        }

        #pragma unroll
        for (int dx = 0; dx < 2 * RMAX + 1; dx++) {
            float4 s = row[dx];
            float sw2 = s.w + ct[dx];
            #pragma unroll
            for (int v = 0; v < V; v++) {
                float t   = fmaf(s.z, cc[v].z, fmaf(s.y, cc[v].y, s.x * cc[v].x));
                float arg = fmaf(t, A, sw2 + rb[v]);
                float w   = ex2f(arg);
                nx[v]  = fmaf(w, s.x, nx[v]);
                ny[v]  = fmaf(w, s.y, ny[v]);
                nz[v]  = fmaf(w, s.z, nz[v]);
                den[v] += w;
            }
        }
    }

    const int ox = blockIdx.x * TW + tx;
    const int oy0 = blockIdx.y * TH + ty * V;
    float* obase = out + (size_t)n * C * HW + ox;
    #pragma unroll
    for (int v = 0; v < V; v++) {
        float inv = __fdividef(1.0f, den[v]);
        float* o = obase + (oy0 + v) * W;
        o[0]      = nx[v] * inv;
        o[HW]     = ny[v] * inv;
        o[2 * HW] = nz[v] * inv;
    }
}

extern "C" void kernel_launch(void* const* d_in, const int* in_sizes, int n_in,
                              void* d_out, int out_size) {
    const float* img    = (const float*)d_in[0];
    const float* params = (const float*)d_in[1];
    float*       outp   = (float*)d_out;
    const int N = in_sizes[1] / 3;   // 8 images
    dim3 block(BX, BY, 1);
    dim3 grid(W / TW, H / TH, N);
    bilateral_kernel<<<grid, block>>>(img, params, outp);
}

// round 3
// speedup vs baseline: 1.2385x; 1.1484x over previous
#include <cuda_runtime.h>

// OriginNoiseBilateral R3: 17x17 bilateral, 8x3x512x512 fp32 NCHW.
// V=4 vertical register blocking; outputs processed as two packed f32x2 pairs
// using Blackwell fma/add/mul.rn.f32x2 (halves FMA-pipe instruction count).
// Pair-granular row peeling removes most of the V-sharing mask waste.

namespace {
constexpr int H = 512, W = 512, C = 3;
constexpr int HW = H * W;
constexpr int RMAX = 8;
constexpr int BX = 32, BY = 8;        // 256 threads
constexpr int V  = 4;                 // vertical outputs per thread (2 pairs)
constexpr int TW = BX;                // 32-wide output tile
constexpr int TH = BY * V;            // 32-tall output tile
constexpr int SW = TW + 2 * RMAX;     // 48
constexpr int SH = TH + 2 * RMAX;     // 48
constexpr int NTAP = 2 * RMAX + 1;    // 17
constexpr float NEG_BIG = -1e30f;
}

typedef unsigned long long u64;

__device__ __forceinline__ float ex2f(float x) {
    float y;
    asm("ex2.approx.ftz.f32 %0, %1;" : "=f"(y) : "f"(x));
    return y;
}
__device__ __forceinline__ u64 pack2(float lo, float hi) {
    u64 r;
    asm("mov.b64 %0, {%1, %2};" : "=l"(r) : "f"(lo), "f"(hi));
    return r;
}
__device__ __forceinline__ void unpack2(u64 v, float& lo, float& hi) {
    asm("mov.b64 {%0, %1}, %2;" : "=f"(lo), "=f"(hi) : "l"(v));
}
__device__ __forceinline__ u64 fma2(u64 a, u64 b, u64 c) {
    u64 d;
    asm("fma.rn.f32x2 %0, %1, %2, %3;" : "=l"(d) : "l"(a), "l"(b), "l"(c));
    return d;
}
__device__ __forceinline__ u64 add2(u64 a, u64 b) {
    u64 d;
    asm("add.rn.f32x2 %0, %1, %2;" : "=l"(d) : "l"(a), "l"(b));
    return d;
}
__device__ __forceinline__ u64 mul2(u64 a, u64 b) {
    u64 d;
    asm("mul.rn.f32x2 %0, %1, %2;" : "=l"(d) : "l"(a), "l"(b));
    return d;
}

struct PairState {
    u64 ccx[2], ccy[2], ccz[2];   // packed center rgb per pair
    u64 nx[2], ny[2], nz[2], dn[2];
    u64 A2;
};

// Process one halo row for the active pairs. row points at this thread's
// leftmost tap; ct holds per-dx spatial terms; rb2 holds packed per-pair
// row bases (-inv2c*|c|^2 + dy^2*(-inv2s), NEG_BIG when masked).
template<bool P01, bool P23>
__device__ __forceinline__ void process_row(const float4* __restrict__ row,
                                            const float* __restrict__ ct,
                                            u64 rb0, u64 rb1, PairState& st)
{
    #pragma unroll
    for (int dx = 0; dx < NTAP; dx++) {
        float4 s = row[dx];
        float sw2 = s.w + ct[dx];
        u64 sx2 = pack2(s.x, s.x);
        u64 sy2 = pack2(s.y, s.y);
        u64 sz2 = pack2(s.z, s.z);
        u64 sw22 = pack2(sw2, sw2);
        if (P01) {
            u64 t   = fma2(sz2, st.ccz[0], fma2(sy2, st.ccy[0], mul2(sx2, st.ccx[0])));
            u64 arg = fma2(t, st.A2, add2(sw22, rb0));
            float a0, a1; unpack2(arg, a0, a1);
            u64 w2 = pack2(ex2f(a0), ex2f(a1));
            st.nx[0] = fma2(w2, sx2, st.nx[0]);
            st.ny[0] = fma2(w2, sy2, st.ny[0]);
            st.nz[0] = fma2(w2, sz2, st.nz[0]);
            st.dn[0] = add2(st.dn[0], w2);
        }
        if (P23) {
            u64 t   = fma2(sz2, st.ccz[1], fma2(sy2, st.ccy[1], mul2(sx2, st.ccx[1])));
            u64 arg = fma2(t, st.A2, add2(sw22, rb1));
            float a0, a1; unpack2(arg, a0, a1);
            u64 w2 = pack2(ex2f(a0), ex2f(a1));
            st.nx[1] = fma2(w2, sx2, st.nx[1]);
            st.ny[1] = fma2(w2, sy2, st.ny[1]);
            st.nz[1] = fma2(w2, sz2, st.nz[1]);
            st.dn[1] = add2(st.dn[1], w2);
        }
    }
}

__global__ __launch_bounds__(256, 2)
void bilateral_kernel(const float* __restrict__ img,
                      const float* __restrict__ params,
                      float* __restrict__ out)
{
    __shared__ float4 tile[SH * SW];   // 36864 B

    const int n   = blockIdx.z;
    const int tx  = threadIdx.x;       // 0..31
    const int ty  = threadIdx.y;       // 0..7
    const int tid = ty * BX + tx;

    const int x0 = blockIdx.x * TW - RMAX;
    const int y0 = blockIdx.y * TH - RMAX;

    const float* im = img + (size_t)n * C * HW;

    // Per-image parameters: window = int(p0)*14+3, sigma = p*99+1
    const float p0 = params[n * 3 + 0];
    const float p1 = params[n * 3 + 1];
    const float p2 = params[n * 3 + 2];
    const int   radius = ((((int)p0) * 14 + 3) - 1) >> 1;
    const int   r      = radius < RMAX ? radius : RMAX;
    const float sc = fmaf(p1, 99.0f, 1.0f);
    const float ss = fmaf(p2, 99.0f, 1.0f);
    const float LOG2E = 1.4426950408889634f;
    // 255^2 (reference pixel scaling) and log2(e) folded into constants.
    const float inv2c = 65025.0f * LOG2E / (2.0f * sc * sc);
    const float inv2s = LOG2E / (2.0f * ss * ss);
    const float A = 2.0f * inv2c;

    // Halo load with edge clamp; .w = -inv2c * |rgb|^2.
    #pragma unroll
    for (int i = tid; i < SH * SW; i += BX * BY) {
        int sy = i / SW, sx = i % SW;
        int gy = min(max(y0 + sy, 0), H - 1);
        int gx = min(max(x0 + sx, 0), W - 1);
        int b  = gy * W + gx;
        float a0 = im[b], a1 = im[b + HW], a2 = im[b + 2 * HW];
        float sq = fmaf(a2, a2, fmaf(a1, a1, a0 * a0));
        tile[i] = make_float4(a0, a1, a2, -inv2c * sq);
    }
    __syncthreads();

    // Per-dx spatial/mask terms (column masking for generic radius).
    float ct[NTAP];
    #pragma unroll
    for (int dx = 0; dx < NTAP; dx++) {
        int d = dx - RMAX;
        int ad = d < 0 ? -d : d;
        ct[dx] = (ad <= r) ? ((float)(d * d)) * (-inv2s) : NEG_BIG;
    }

    // Centers for this thread's V outputs.
    float4 cc[V];
    #pragma unroll
    for (int v = 0; v < V; v++)
        cc[v] = tile[(ty * V + v + RMAX) * SW + (tx + RMAX)];

    PairState st;
    st.A2 = pack2(A, A);
    #pragma unroll
    for (int p = 0; p < 2; p++) {
        st.ccx[p] = pack2(cc[2*p].x, cc[2*p+1].x);
        st.ccy[p] = pack2(cc[2*p].y, cc[2*p+1].y);
        st.ccz[p] = pack2(cc[2*p].z, cc[2*p+1].z);
        st.nx[p] = st.ny[p] = st.nz[p] = st.dn[p] = pack2(0.0f, 0.0f);
    }
    float cw[V];
    #pragma unroll
    for (int v = 0; v < V; v++) cw[v] = cc[v].w;

    // Sliding window over V + 2*RMAX rows.
    #pragma unroll 1
    for (int i = 0; i < V + 2 * RMAX; i++) {
        const float4* row = &tile[(ty * V + i) * SW + tx];

        float rb[V];
        #pragma unroll
        for (int v = 0; v < V; v++) {
            int dy = i - RMAX - v;
            int ady = dy < 0 ? -dy : dy;
            rb[v] = (ady <= r) ? fmaf((float)(dy * dy), -inv2s, cw[v]) : NEG_BIG;
        }
        u64 rb0 = pack2(rb[0], rb[1]);
        u64 rb1 = pack2(rb[2], rb[3]);

        if (i < 2)                  process_row<true, false>(row, ct, rb0, rb1, st);
        else if (i > 2 * RMAX + 1)  process_row<false, true>(row, ct, rb0, rb1, st);
        else                        process_row<true, true >(row, ct, rb0, rb1, st);
    }

    const int ox  = blockIdx.x * TW + tx;
    const int oy0 = blockIdx.y * TH + ty * V;
    float* obase = out + (size_t)n * C * HW + ox;
    #pragma unroll
    for (int p = 0; p < 2; p++) {
        float nxl, nxh, nyl, nyh, nzl, nzh, dl, dh;
        unpack2(st.nx[p], nxl, nxh);
        unpack2(st.ny[p], nyl, nyh);
        unpack2(st.nz[p], nzl, nzh);
        unpack2(st.dn[p], dl, dh);
        float il = __fdividef(1.0f, dl);
        float ih = __fdividef(1.0f, dh);
        float* o0 = obase + (oy0 + 2*p) * W;
        float* o1 = obase + (oy0 + 2*p + 1) * W;
        o0[0] = nxl * il;  o0[HW] = nyl * il;  o0[2*HW] = nzl * il;
        o1[0] = nxh * ih;  o1[HW] = nyh * ih;  o1[2*HW] = nzh * ih;
    }
}

extern "C" void kernel_launch(void* const* d_in, const int* in_sizes, int n_in,
                              void* d_out, int out_size) {
    const float* img    = (const float*)d_in[0];
    const float* params = (const float*)d_in[1];
    float*       outp   = (float*)d_out;
    const int N = in_sizes[1] / 3;   // 8 images
    dim3 block(BX, BY, 1);
    dim3 grid(W / TW, H / TH, N);
    bilateral_kernel<<<grid, block>>>(img, params, outp);
}

// round 4
// speedup vs baseline: 1.3153x; 1.0620x over previous
#include <cuda_runtime.h>

// OriginNoiseBilateral R4: 17x17 bilateral, 8x3x512x512 fp32 NCHW.
// Hot kernel (radius==8): V=4 vertical blocking, packed f32x2 math with A
// folded into center colors (8 packed ops/pair/tap), no ct[] array
// (immediate dx^2), 3 CTAs/SM. Generic kernel handles radius<8 (separate
// launch, per-block early exit keeps register allocations independent).

namespace {
constexpr int H = 512, W = 512, C = 3;
constexpr int HW = H * W;
constexpr int RMAX = 8;
constexpr int BX = 32, BY = 8;        // 256 threads
constexpr int V  = 4;                 // vertical outputs per thread (2 pairs)
constexpr int TW = BX;                // 32-wide output tile
constexpr int TH = BY * V;            // 32-tall output tile
constexpr int SW = TW + 2 * RMAX;     // 48
constexpr int SH = TH + 2 * RMAX;     // 48
constexpr int NTAP = 2 * RMAX + 1;    // 17
constexpr float NEG_BIG = -1e30f;
constexpr float LOG2E = 1.4426950408889634f;
}

typedef unsigned long long u64;

__device__ __forceinline__ float ex2f(float x) {
    float y;
    asm("ex2.approx.ftz.f32 %0, %1;" : "=f"(y) : "f"(x));
    return y;
}
__device__ __forceinline__ u64 pack2(float lo, float hi) {
    u64 r;
    asm("mov.b64 %0, {%1, %2};" : "=l"(r) : "f"(lo), "f"(hi));
    return r;
}
__device__ __forceinline__ void unpack2(u64 v, float& lo, float& hi) {
    asm("mov.b64 {%0, %1}, %2;" : "=f"(lo), "=f"(hi) : "l"(v));
}
__device__ __forceinline__ u64 fma2(u64 a, u64 b, u64 c) {
    u64 d;
    asm("fma.rn.f32x2 %0, %1, %2, %3;" : "=l"(d) : "l"(a), "l"(b), "l"(c));
    return d;
}
__device__ __forceinline__ u64 add2(u64 a, u64 b) {
    u64 d;
    asm("add.rn.f32x2 %0, %1, %2;" : "=l"(d) : "l"(a), "l"(b));
    return d;
}

struct PairState {
    u64 ccx[2], ccy[2], ccz[2];   // packed A-scaled center rgb per pair
    u64 nx[2], ny[2], nz[2], dn[2];
};

// One halo row. dx^2 terms are compile-time immediates (radius==8 hot path).
template<bool P01, bool P23>
__device__ __forceinline__ void process_row(const float4* __restrict__ row,
                                            float m /* -inv2s */,
                                            u64 rb0, u64 rb1, PairState& st)
{
    #pragma unroll
    for (int dx = 0; dx < NTAP; dx++) {
        float4 s = row[dx];
        const float d2 = (float)((dx - RMAX) * (dx - RMAX));
        float sw2 = fmaf(d2, m, s.w);          // FFMA-imm
        u64 sw22 = pack2(sw2, sw2);
        u64 sx2  = pack2(s.x, s.x);
        u64 sy2  = pack2(s.y, s.y);
        u64 sz2  = pack2(s.z, s.z);
        if (P01) {
            u64 arg = fma2(sz2, st.ccz[0],
                      fma2(sy2, st.ccy[0],
                      fma2(sx2, st.ccx[0], add2(sw22, rb0))));
            float a0, a1; unpack2(arg, a0, a1);
            u64 w2 = pack2(ex2f(a0), ex2f(a1));
            st.nx[0] = fma2(w2, sx2, st.nx[0]);
            st.ny[0] = fma2(w2, sy2, st.ny[0]);
            st.nz[0] = fma2(w2, sz2, st.nz[0]);
            st.dn[0] = add2(st.dn[0], w2);
        }
        if (P23) {
            u64 arg = fma2(sz2, st.ccz[1],
                      fma2(sy2, st.ccy[1],
                      fma2(sx2, st.ccx[1], add2(sw22, rb1))));
            float a0, a1; unpack2(arg, a0, a1);
            u64 w2 = pack2(ex2f(a0), ex2f(a1));
            st.nx[1] = fma2(w2, sx2, st.nx[1]);
            st.ny[1] = fma2(w2, sy2, st.ny[1]);
            st.nz[1] = fma2(w2, sz2, st.nz[1]);
            st.dn[1] = add2(st.dn[1], w2);
        }
    }
}

// ---------------- Hot kernel: radius == RMAX only ----------------
__global__ __launch_bounds__(256, 3)
void bilateral_hot(const float* __restrict__ img,
                   const float* __restrict__ params,
                   float* __restrict__ out)
{
    const int n = blockIdx.z;
    const int radius = ((((int)params[n * 3 + 0]) * 14 + 3) - 1) >> 1;
    if (radius < RMAX) return;                 // uniform per block

    __shared__ float4 tile[SH * SW];           // 36864 B

    const int tx  = threadIdx.x;
    const int ty  = threadIdx.y;
    const int tid = ty * BX + tx;

    const int x0 = blockIdx.x * TW - RMAX;
    const int y0 = blockIdx.y * TH - RMAX;

    const float* im = img + (size_t)n * C * HW;

    const float p1 = params[n * 3 + 1];
    const float p2 = params[n * 3 + 2];
    const float sc = fmaf(p1, 99.0f, 1.0f);
    const float ss = fmaf(p2, 99.0f, 1.0f);
    const float inv2c = 65025.0f * LOG2E / (2.0f * sc * sc); // 255^2, log2e folded
    const float inv2s = LOG2E / (2.0f * ss * ss);
    const float m = -inv2s;
    const float A = 2.0f * inv2c;

    // Halo load with edge clamp; .w = -inv2c * |rgb|^2.
    #pragma unroll
    for (int i = tid; i < SH * SW; i += BX * BY) {
        int sy = i / SW, sx = i % SW;
        int gy = min(max(y0 + sy, 0), H - 1);
        int gx = min(max(x0 + sx, 0), W - 1);
        int b  = gy * W + gx;
        float a0 = im[b], a1 = im[b + HW], a2 = im[b + 2 * HW];
        float sq = fmaf(a2, a2, fmaf(a1, a1, a0 * a0));
        tile[i] = make_float4(a0, a1, a2, -inv2c * sq);
    }
    __syncthreads();

    float4 cc[V];
    #pragma unroll
    for (int v = 0; v < V; v++)
        cc[v] = tile[(ty * V + v + RMAX) * SW + (tx + RMAX)];

    PairState st;
    #pragma unroll
    for (int p = 0; p < 2; p++) {
        st.ccx[p] = pack2(A * cc[2*p].x, A * cc[2*p+1].x);
        st.ccy[p] = pack2(A * cc[2*p].y, A * cc[2*p+1].y);
        st.ccz[p] = pack2(A * cc[2*p].z, A * cc[2*p+1].z);
        st.nx[p] = st.ny[p] = st.nz[p] = st.dn[p] = pack2(0.0f, 0.0f);
    }
    float cw0 = cc[0].w, cw1 = cc[1].w, cw2 = cc[2].w, cw3 = cc[3].w;

    #pragma unroll 1
    for (int i = 0; i < V + 2 * RMAX; i++) {
        const float4* row = &tile[(ty * V + i) * SW + tx];

        // Per-v row base: dy^2 * (-inv2s) + cc.w, NEG_BIG outside |dy|<=8.
        int dy0 = i - RMAX;
        float rbv[V];
        #pragma unroll
        for (int v = 0; v < V; v++) {
            int dy = dy0 - v;
            rbv[v] = (dy >= -RMAX && dy <= RMAX)
                   ? fmaf((float)(dy * dy), m,
                          (v == 0 ? cw0 : v == 1 ? cw1 : v == 2 ? cw2 : cw3))
                   : NEG_BIG;
        }
        u64 rb0 = pack2(rbv[0], rbv[1]);
        u64 rb1 = pack2(rbv[2], rbv[3]);

        if (i < 2)                 process_row<true , false>(row, m, rb0, rb1, st);
        else if (i > 2 * RMAX + 1) process_row<false, true >(row, m, rb0, rb1, st);
        else                       process_row<true , true >(row, m, rb0, rb1, st);
    }

    const int ox  = blockIdx.x * TW + tx;
    const int oy0 = blockIdx.y * TH + ty * V;
    float* obase = out + (size_t)n * C * HW + ox;
    #pragma unroll
    for (int p = 0; p < 2; p++) {
        float nxl, nxh, nyl, nyh, nzl, nzh, dl, dh;
        unpack2(st.nx[p], nxl, nxh);
        unpack2(st.ny[p], nyl, nyh);
        unpack2(st.nz[p], nzl, nzh);
        unpack2(st.dn[p], dl, dh);
        float il = __fdividef(1.0f, dl);
        float ih = __fdividef(1.0f, dh);
        float* o0 = obase + (oy0 + 2*p) * W;
        float* o1 = obase + (oy0 + 2*p + 1) * W;
        o0[0] = nxl * il;  o0[HW] = nyl * il;  o0[2*HW] = nzl * il;
        o1[0] = nxh * ih;  o1[HW] = nyh * ih;  o1[2*HW] = nzh * ih;
    }
}

// ---------------- Generic kernel: radius < RMAX ----------------
namespace { constexpr int GT = 16, GS = GT + 2 * RMAX; }

__global__ __launch_bounds__(256)
void bilateral_generic(const float* __restrict__ img,
                       const float* __restrict__ params,
                       float* __restrict__ out)
{
    const int n = blockIdx.z;
    const int radius = ((((int)params[n * 3 + 0]) * 14 + 3) - 1) >> 1;
    const int r = radius < RMAX ? radius : RMAX;
    if (radius >= RMAX) return;                 // hot kernel handles it

    __shared__ float4 tile[GS * GS];

    const int tx  = threadIdx.x;
    const int ty  = threadIdx.y;
    const int tid = ty * GT + tx;
    const int x0 = blockIdx.x * GT - RMAX;
    const int y0 = blockIdx.y * GT - RMAX;
    const float* im = img + (size_t)n * C * HW;

    const float p1 = params[n * 3 + 1];
    const float p2 = params[n * 3 + 2];
    const float sc = fmaf(p1, 99.0f, 1.0f);
    const float ss = fmaf(p2, 99.0f, 1.0f);
    const float inv2c = 65025.0f * LOG2E / (2.0f * sc * sc);
    const float inv2s = LOG2E / (2.0f * ss * ss);

    #pragma unroll
    for (int i = tid; i < GS * GS; i += 256) {
        int sy = i / GS, sx = i % GS;
        int gy = min(max(y0 + sy, 0), H - 1);
        int gx = min(max(x0 + sx, 0), W - 1);
        int b  = gy * W + gx;
        tile[i] = make_float4(im[b], im[b + HW], im[b + 2 * HW], 0.0f);
    }
    __syncthreads();

    const float4 c = tile[(ty + RMAX) * GS + (tx + RMAX)];
    float n0 = 0.0f, n1 = 0.0f, n2 = 0.0f, den = 0.0f;

    for (int dy = -r; dy <= r; dy++) {
        const float4* row = &tile[(ty + RMAX + dy) * GS + (tx + RMAX)];
        const float spy = (float)(dy * dy);
        for (int dx = -r; dx <= r; dx++) {
            float4 s  = row[dx];
            float d0 = s.x - c.x, d1 = s.y - c.y, d2 = s.z - c.z;
            float dist2 = fmaf(d2, d2, fmaf(d1, d1, d0 * d0));
            float sp2   = spy + (float)(dx * dx);
            float w = ex2f(fmaf(dist2, -inv2c, sp2 * (-inv2s)));
            n0 = fmaf(w, s.x, n0);
            n1 = fmaf(w, s.y, n1);
            n2 = fmaf(w, s.z, n2);
            den += w;
        }
    }

    const int ox = blockIdx.x * GT + tx;
    const int oy = blockIdx.y * GT + ty;
    float inv = __fdividef(1.0f, den);
    float* o = out + (size_t)n * C * HW + oy * W + ox;
    o[0] = n0 * inv;  o[HW] = n1 * inv;  o[2 * HW] = n2 * inv;
}

extern "C" void kernel_launch(void* const* d_in, const int* in_sizes, int n_in,
                              void* d_out, int out_size) {
    const float* img    = (const float*)d_in[0];
    const float* params = (const float*)d_in[1];
    float*       outp   = (float*)d_out;
    const int N = in_sizes[1] / 3;   // 8 images

    dim3 hb(BX, BY, 1);
    dim3 hg(W / TW, H / TH, N);
    bilateral_hot<<<hg, hb>>>(img, params, outp);

    dim3 gb(GT, GT, 1);
    dim3 gg(W / GT, H / GT, N);
    bilateral_generic<<<gg, gb>>>(img, params, outp);
}

// round 5
// speedup vs baseline: 1.3255x; 1.0078x over previous
#include <cuda_runtime.h>

// OriginNoiseBilateral R5: 17x17 bilateral, 8x3x512x512 fp32 NCHW.
// Single kernel. Hot path (radius==8): V=4 vertical blocking, packed f32x2
// math (8 packed ops/pair/tap), dx^2 as FFMA immediates, pair-peeled edge
// rows. Cold generic path (radius<8) is a tiny runtime-looped scalar branch.
// __launch_bounds__(256,4) targets 64 regs -> 4 CTAs/SM (32 warps) to cover
// the fma2-chain + EX2 latency that limited R4 (issue 54%).

namespace {
constexpr int H = 512, W = 512, C = 3;
constexpr int HW = H * W;
constexpr int RMAX = 8;
constexpr int BX = 32, BY = 8;        // 256 threads
constexpr int V  = 4;                 // vertical outputs per thread (2 pairs)
constexpr int TW = BX;                // 32-wide output tile
constexpr int TH = BY * V;            // 32-tall output tile
constexpr int SW = TW + 2 * RMAX;     // 48
constexpr int SH = TH + 2 * RMAX;     // 48
constexpr int NTAP = 2 * RMAX + 1;    // 17
constexpr float NEG_BIG = -1e30f;
constexpr float LOG2E = 1.4426950408889634f;
}

typedef unsigned long long u64;

__device__ __forceinline__ float ex2f(float x) {
    float y;
    asm("ex2.approx.ftz.f32 %0, %1;" : "=f"(y) : "f"(x));
    return y;
}
__device__ __forceinline__ u64 pack2(float lo, float hi) {
    u64 r;
    asm("mov.b64 %0, {%1, %2};" : "=l"(r) : "f"(lo), "f"(hi));
    return r;
}
__device__ __forceinline__ void unpack2(u64 v, float& lo, float& hi) {
    asm("mov.b64 {%0, %1}, %2;" : "=f"(lo), "=f"(hi) : "l"(v));
}
__device__ __forceinline__ u64 fma2(u64 a, u64 b, u64 c) {
    u64 d;
    asm("fma.rn.f32x2 %0, %1, %2, %3;" : "=l"(d) : "l"(a), "l"(b), "l"(c));
    return d;
}
__device__ __forceinline__ u64 add2(u64 a, u64 b) {
    u64 d;
    asm("add.rn.f32x2 %0, %1, %2;" : "=l"(d) : "l"(a), "l"(b));
    return d;
}

struct PairState {
    u64 ccx[2], ccy[2], ccz[2];   // packed A-scaled center rgb per pair
    u64 nx[2], ny[2], nz[2], dn[2];
};

// One halo row. dx^2 terms are compile-time immediates (radius==8 hot path).
template<bool P01, bool P23>
__device__ __forceinline__ void process_row(const float4* __restrict__ row,
                                            float m /* -inv2s */,
                                            u64 rb0, u64 rb1, PairState& st)
{
    #pragma unroll
    for (int dx = 0; dx < NTAP; dx++) {
        float4 s = row[dx];
        const float d2 = (float)((dx - RMAX) * (dx - RMAX));
        float sw2 = fmaf(d2, m, s.w);          // FFMA-imm
        u64 sw22 = pack2(sw2, sw2);
        u64 sx2  = pack2(s.x, s.x);
        u64 sy2  = pack2(s.y, s.y);
        u64 sz2  = pack2(s.z, s.z);
        if (P01) {
            u64 arg = fma2(sz2, st.ccz[0],
                      fma2(sy2, st.ccy[0],
                      fma2(sx2, st.ccx[0], add2(sw22, rb0))));
            float a0, a1; unpack2(arg, a0, a1);
            u64 w2 = pack2(ex2f(a0), ex2f(a1));
            st.nx[0] = fma2(w2, sx2, st.nx[0]);
            st.ny[0] = fma2(w2, sy2, st.ny[0]);
            st.nz[0] = fma2(w2, sz2, st.nz[0]);
            st.dn[0] = add2(st.dn[0], w2);
        }
        if (P23) {
            u64 arg = fma2(sz2, st.ccz[1],
                      fma2(sy2, st.ccy[1],
                      fma2(sx2, st.ccx[1], add2(sw22, rb1))));
            float a0, a1; unpack2(arg, a0, a1);
            u64 w2 = pack2(ex2f(a0), ex2f(a1));
            st.nx[1] = fma2(w2, sx2, st.nx[1]);
            st.ny[1] = fma2(w2, sy2, st.ny[1]);
            st.nz[1] = fma2(w2, sz2, st.nz[1]);
            st.dn[1] = add2(st.dn[1], w2);
        }
    }
}

__global__ __launch_bounds__(256, 4)
void bilateral_kernel(const float* __restrict__ img,
                      const float* __restrict__ params,
                      float* __restrict__ out)
{
    __shared__ float4 tile[SH * SW];           // 36864 B

    const int n   = blockIdx.z;
    const int tx  = threadIdx.x;
    const int ty  = threadIdx.y;
    const int tid = ty * BX + tx;

    const int x0 = blockIdx.x * TW - RMAX;
    const int y0 = blockIdx.y * TH - RMAX;

    const float* im = img + (size_t)n * C * HW;

    const int radius = ((((int)params[n * 3 + 0]) * 14 + 3) - 1) >> 1;
    const int r = radius < RMAX ? radius : RMAX;
    const float p1 = params[n * 3 + 1];
    const float p2 = params[n * 3 + 2];
    const float sc = fmaf(p1, 99.0f, 1.0f);
    const float ss = fmaf(p2, 99.0f, 1.0f);
    // 255^2 (reference pixel scaling) and log2(e) folded into constants.
    const float inv2c = 65025.0f * LOG2E / (2.0f * sc * sc);
    const float inv2s = LOG2E / (2.0f * ss * ss);
    const float m = -inv2s;
    const float A = 2.0f * inv2c;

    // Halo load with edge clamp; .w = -inv2c * |rgb|^2.
    #pragma unroll
    for (int i = tid; i < SH * SW; i += BX * BY) {
        int sy = i / SW, sx = i % SW;
        int gy = min(max(y0 + sy, 0), H - 1);
        int gx = min(max(x0 + sx, 0), W - 1);
        int b  = gy * W + gx;
        float a0 = im[b], a1 = im[b + HW], a2 = im[b + 2 * HW];
        float sq = fmaf(a2, a2, fmaf(a1, a1, a0 * a0));
        tile[i] = make_float4(a0, a1, a2, -inv2c * sq);
    }
    __syncthreads();

    float* obase = out + (size_t)n * C * HW + blockIdx.x * TW + tx;
    const int oy0 = blockIdx.y * TH + ty * V;

    if (r == RMAX) {
        // ---------------- Hot path ----------------
        float4 cc[V];
        #pragma unroll
        for (int v = 0; v < V; v++)
            cc[v] = tile[(ty * V + v + RMAX) * SW + (tx + RMAX)];

        PairState st;
        #pragma unroll
        for (int p = 0; p < 2; p++) {
            st.ccx[p] = pack2(A * cc[2*p].x, A * cc[2*p+1].x);
            st.ccy[p] = pack2(A * cc[2*p].y, A * cc[2*p+1].y);
            st.ccz[p] = pack2(A * cc[2*p].z, A * cc[2*p+1].z);
            st.nx[p] = st.ny[p] = st.nz[p] = st.dn[p] = pack2(0.0f, 0.0f);
        }
        u64 cw01 = pack2(cc[0].w, cc[1].w);
        u64 cw23 = pack2(cc[2].w, cc[3].w);

        const float4* row = &tile[(ty * V) * SW + tx];

        #pragma unroll 1
        for (int i = 0; i < V + 2 * RMAX; i++) {
            // Per-v row base: dy^2*m + cc.w; NEG_BIG outside |dy|<=8.
            int dy0 = i - RMAX;
            float c0, c1, c2, c3;
            unpack2(cw01, c0, c1);
            unpack2(cw23, c2, c3);
            float rv0 = (dy0 <= RMAX)                          ? fmaf((float)(dy0 * dy0), m, c0) : NEG_BIG;
            int dy1 = dy0 - 1;
            float rv1 = (dy1 >= -RMAX && dy1 <= RMAX)          ? fmaf((float)(dy1 * dy1), m, c1) : NEG_BIG;
            int dy2 = dy0 - 2;
            float rv2 = (dy2 >= -RMAX && dy2 <= RMAX)          ? fmaf((float)(dy2 * dy2), m, c2) : NEG_BIG;
            int dy3 = dy0 - 3;
            float rv3 = (dy3 >= -RMAX)                         ? fmaf((float)(dy3 * dy3), m, c3) : NEG_BIG;
            u64 rb0 = pack2(rv0, rv1);
            u64 rb1 = pack2(rv2, rv3);

            if (i < 2)                 process_row<true , false>(row, m, rb0, rb1, st);
            else if (i > 2 * RMAX + 1) process_row<false, true >(row, m, rb0, rb1, st);
            else                       process_row<true , true >(row, m, rb0, rb1, st);
            row += SW;
        }

        #pragma unroll
        for (int p = 0; p < 2; p++) {
            float nxl, nxh, nyl, nyh, nzl, nzh, dl, dh;
            unpack2(st.nx[p], nxl, nxh);
            unpack2(st.ny[p], nyl, nyh);
            unpack2(st.nz[p], nzl, nzh);
            unpack2(st.dn[p], dl, dh);
            float il = __fdividef(1.0f, dl);
            float ih = __fdividef(1.0f, dh);
            float* o0 = obase + (oy0 + 2*p) * W;
            float* o1 = obase + (oy0 + 2*p + 1) * W;
            o0[0] = nxl * il;  o0[HW] = nyl * il;  o0[2*HW] = nzl * il;
            o1[0] = nxh * ih;  o1[HW] = nyh * ih;  o1[2*HW] = nzh * ih;
        }
    } else {
        // ---------------- Cold generic path (radius < 8) ----------------
        #pragma unroll 1
        for (int v = 0; v < V; v++) {
            const float4 c = tile[(ty * V + v + RMAX) * SW + (tx + RMAX)];
            float n0 = 0.0f, n1 = 0.0f, n2 = 0.0f, den = 0.0f;
            #pragma unroll 1
            for (int dy = -r; dy <= r; dy++) {
                const float4* grow = &tile[(ty * V + v + RMAX + dy) * SW + (tx + RMAX)];
                const float spy = (float)(dy * dy);
                #pragma unroll 1
                for (int dx = -r; dx <= r; dx++) {
                    float4 s = grow[dx];
                    float t = fmaf(s.z, c.z, fmaf(s.y, c.y, s.x * c.x));
                    float sp2 = spy + (float)(dx * dx);
                    float arg = fmaf(t, A, fmaf(sp2, m, s.w + c.w));
                    float w = ex2f(arg);
                    n0 = fmaf(w, s.x, n0);
                    n1 = fmaf(w, s.y, n1);
                    n2 = fmaf(w, s.z, n2);
                    den += w;
                }
            }
            float inv = __fdividef(1.0f, den);
            float* o = obase + (oy0 + v) * W;
            o[0] = n0 * inv;  o[HW] = n1 * inv;  o[2*HW] = n2 * inv;
        }
    }
}

extern "C" void kernel_launch(void* const* d_in, const int* in_sizes, int n_in,
                              void* d_out, int out_size) {
    const float* img    = (const float*)d_in[0];
    const float* params = (const float*)d_in[1];
    float*       outp   = (float*)d_out;
    const int N = in_sizes[1] / 3;   // 8 images
    dim3 block(BX, BY, 1);
    dim3 grid(W / TW, H / TH, N);
    bilateral_kernel<<<grid, block>>>(img, params, outp);
}